// round 16
// baseline (speedup 1.0000x reference)
#include <cuda_runtime.h>
#include <cuda_fp16.h>
#include <cstdint>

#define SEQ 2048
#define DIM 128
#define BHN 32
#define NROWS (BHN * SEQ)   // 65536 rows each for q and k

#define BH_CHUNK 4                      // heads per pipeline chunk
#define NCHUNK (BHN / BH_CHUNK)         // 8 chunks
#define ROWS_PER_CHUNK (BH_CHUNK * SEQ) // 8192 rows of q (and of k)

// Normalized + sqrt(scale)-folded fp16 copies (16 MB each, device globals)
__device__ __half g_qh[(size_t)NROWS * DIM];
__device__ __half g_kh[(size_t)NROWS * DIM];

// ---------------------------------------------------------------------------
// Kernel 1: per-row normalize, fold sqrt(log2e/temp), convert to fp16.
// One warp per row. Processes rows [row_base, row_base + ROWS_PER_CHUNK)
// of BOTH q and k. Streaming loads: fp32 inputs are read exactly once.
// ---------------------------------------------------------------------------
__global__ void norm_cvt_kernel(const float* __restrict__ q,
                                const float* __restrict__ k,
                                const float* __restrict__ logt,
                                int row_base) {
    int gwarp = (blockIdx.x * blockDim.x + threadIdx.x) >> 5;
    int lane = threadIdx.x & 31;
    bool is_q = gwarp < ROWS_PER_CHUNK;
    int row = row_base + (is_q ? gwarp : gwarp - ROWS_PER_CHUNK);
    const float* src = is_q ? q : k;
    float4 v = __ldcs(reinterpret_cast<const float4*>(src + (size_t)row * DIM) + lane);
    float ss = v.x * v.x + v.y * v.y + v.z * v.z + v.w * v.w;
#pragma unroll
    for (int o = 16; o > 0; o >>= 1) ss += __shfl_xor_sync(0xffffffffu, ss, o);

    const float LOG2E = 1.442695040888963f;
    float temp = fminf(fmaxf(__expf(*logt), 0.05f), 100.0f);
    float rsc = sqrtf(LOG2E / temp);
    float f = rsc / fmaxf(sqrtf(ss), 1e-12f);

    __half2 h0 = __floats2half2_rn(v.x * f, v.y * f);
    __half2 h1 = __floats2half2_rn(v.z * f, v.w * f);
    __half* dst = (is_q ? g_qh : g_kh) + (size_t)row * DIM + lane * 4;
    uint2 u;
    u.x = *reinterpret_cast<uint32_t*>(&h0);
    u.y = *reinterpret_cast<uint32_t*>(&h1);
    *reinterpret_cast<uint2*>(dst) = u;
}

// ---------------------------------------------------------------------------
// Helpers
// ---------------------------------------------------------------------------
__device__ __forceinline__ uint32_t smem_to_u32(const void* p) {
    uint32_t a;
    asm("{ .reg .u64 t; cvta.to.shared.u64 t, %1; cvt.u32.u64 %0, t; }" : "=r"(a) : "l"(p));
    return a;
}

// .ca: keep fills in L1 — A/B (round 15) proved cross-CTA tile reuse wins
#define CP_ASYNC16(dst, src) \
    asm volatile("cp.async.ca.shared.global [%0], [%1], 16;" :: "r"(dst), "l"(src))
#define CP_COMMIT() asm volatile("cp.async.commit_group;" ::: "memory")
#define CP_WAIT(n)  asm volatile("cp.async.wait_group %0;" :: "n"(n) : "memory")

__device__ __forceinline__ void ldsm_x4(unsigned r[4], uint32_t addr) {
    asm volatile("ldmatrix.sync.aligned.m8n8.x4.shared.b16 {%0,%1,%2,%3}, [%4];"
                 : "=r"(r[0]), "=r"(r[1]), "=r"(r[2]), "=r"(r[3]) : "r"(addr));
}

__device__ __forceinline__ void mma_f16(float c[4], const unsigned a[4],
                                        unsigned b0, unsigned b1) {
    asm volatile(
        "mma.sync.aligned.m16n8k16.row.col.f32.f16.f16.f32 "
        "{%0,%1,%2,%3}, {%4,%5,%6,%7}, {%8,%9}, {%0,%1,%2,%3};\n"
        : "+f"(c[0]), "+f"(c[1]), "+f"(c[2]), "+f"(c[3])
        : "r"(a[0]), "r"(a[1]), "r"(a[2]), "r"(a[3]), "r"(b0), "r"(b1));
}

__device__ __forceinline__ float ex2f(float x) {
    float y;
    asm("ex2.approx.f32 %0, %1;" : "=f"(y) : "f"(x));
    return y;
}

// streaming store: output is written once, never re-read -> evict-first in L2
__device__ __forceinline__ void stg_cs_v2(float* p, float x, float y) {
    asm volatile("st.global.cs.v2.f32 [%0], {%1, %2};" :: "l"(p), "f"(x), "f"(y) : "memory");
}

// ---------------------------------------------------------------------------
// Kernel 2: fp16 GEMM + exp epilogue (round-13 configuration, bh-chunked).
// 2 CTAs/SM, 256 threads. CTA tile M=128 x N=128, K=128 in two chunks of
// 64, 2 smem stages. Warp grid 2x4, warp tile 64x32. In-warp fragment
// software pipeline; fused-tail epilogue under the last k-step's MMAs.
// smem stage = 36864 B, total 73728 B -> 2 CTAs/SM.
// acc is in log2 domain: epilogue = ex2(acc) + 1e-6.
// ---------------------------------------------------------------------------
#define LDH 72
#define CH_BYTES (128 * LDH * 2)          // 18432
#define STAGE_BYTES (2 * CH_BYTES)        // 36864
#define SMEM_TOTAL (2 * STAGE_BYTES)      // 73728

__global__ __launch_bounds__(256, 2) void hgemm_exp_kernel(float* __restrict__ out,
                                                           int bh_base) {
    extern __shared__ char smem[];
    uint32_t sbase = smem_to_u32(smem);

    int bh = bh_base + blockIdx.z;
    int bm = blockIdx.y;
    int bn = blockIdx.x;
    int tid = threadIdx.x;
    int warp = tid >> 5, lane = tid & 31;
    int wm = warp >> 2, wn = warp & 3;   // 2 x 4 warp grid
    int wmo = wm * 64, wno = wn * 32;    // warp tile 64 x 32

    const __half* qb = g_qh + ((size_t)bh * SEQ + (size_t)bm * 128) * DIM;
    const __half* kb = g_kh + ((size_t)bh * SEQ + (size_t)bn * 128) * DIM;

    // cp.async: chunk matrix = 128 rows x 64 halves = 1024 16B-chunks -> 4/thr
    int ldr = tid >> 3;          // base row 0..31
    int ldc8 = tid & 7;          // 8-half column group

    auto issue_chunk = [&](int c, int s) {
        uint32_t stA = sbase + (uint32_t)(s * STAGE_BYTES);
        uint32_t stB = stA + CH_BYTES;
        const __half* qsrc = qb + c * 64 + ldc8 * 8;
        const __half* ksrc = kb + c * 64 + ldc8 * 8;
#pragma unroll
        for (int i = 0; i < 4; i++) {
            int r = ldr + i * 32;
            uint32_t o = (uint32_t)((r * LDH + ldc8 * 8) * 2);
            CP_ASYNC16(stA + o, qsrc + (size_t)r * DIM);
            CP_ASYNC16(stB + o, ksrc + (size_t)r * DIM);
        }
        CP_COMMIT();
    };

    issue_chunk(0, 0);
    issue_chunk(1, 1);

    // fragment offsets within a stage (halves*2 = bytes)
    int l15 = lane & 15, lk = (lane >> 4) * 8;
    uint32_t aOff[4], bOff[2];
#pragma unroll
    for (int mi = 0; mi < 4; mi++)
        aOff[mi] = (uint32_t)(((wmo + mi * 16 + l15) * LDH + lk) * 2);
#pragma unroll
    for (int p = 0; p < 2; p++)
        bOff[p] = (uint32_t)(((wno + p * 16 + l15) * LDH + lk) * 2) + CH_BYTES;

    float acc[4][4][4];
#pragma unroll
    for (int mi = 0; mi < 4; mi++)
#pragma unroll
        for (int ni = 0; ni < 4; ni++)
#pragma unroll
            for (int r = 0; r < 4; r++) acc[mi][ni][r] = 0.0f;

    unsigned af[2][4][4], bf[2][2][4];

    // per-mi MMA group for k-step buffer `cur`
    auto mma_mi = [&](int cur, int mi) {
#pragma unroll
        for (int p = 0; p < 2; p++) {
            mma_f16(acc[mi][2 * p],     af[cur][mi], bf[cur][p][0], bf[cur][p][2]);
            mma_f16(acc[mi][2 * p + 1], af[cur][mi], bf[cur][p][1], bf[cur][p][3]);
        }
    };

    // epilogue store base: row (bm*128 + wmo + gid), col (bn*128 + wno + tig*2)
    int gid = lane >> 2, tig = lane & 3;
    float* bp = out + ((size_t)bh * SEQ + (size_t)(bm * 128 + wmo + gid)) * SEQ
                    + bn * 128 + wno + tig * 2;

    // per-mi epilogue: 16 ex2 + 8 stg.cs.v2
    auto epi_mi = [&](int mi) {
        float* o0p = bp + (size_t)(mi * 16) * SEQ;
        float* o1p = o0p + (size_t)8 * SEQ;
#pragma unroll
        for (int ni = 0; ni < 4; ni++) {
            stg_cs_v2(o0p, ex2f(acc[mi][ni][0]) + 1e-6f,
                           ex2f(acc[mi][ni][1]) + 1e-6f);
            stg_cs_v2(o1p, ex2f(acc[mi][ni][2]) + 1e-6f,
                           ex2f(acc[mi][ni][3]) + 1e-6f);
            o0p += 8; o1p += 8;
        }
    };

    // ---- chunk 0: 4 ksteps, fragments pipelined one step ahead ----
    CP_WAIT(1);
    __syncthreads();
    {
        uint32_t st = sbase;
#pragma unroll
        for (int mi = 0; mi < 4; mi++) ldsm_x4(af[0][mi], st + aOff[mi]);
#pragma unroll
        for (int p = 0; p < 2; p++) ldsm_x4(bf[0][p], st + bOff[p]);
#pragma unroll
        for (int s = 0; s < 4; s++) {
            int cur = s & 1, nxt = cur ^ 1;
            if (s < 3) {
                uint32_t kb32 = (uint32_t)((s + 1) * 32);
#pragma unroll
                for (int mi = 0; mi < 4; mi++) ldsm_x4(af[nxt][mi], st + aOff[mi] + kb32);
#pragma unroll
                for (int p = 0; p < 2; p++) ldsm_x4(bf[nxt][p], st + bOff[p] + kb32);
            }
#pragma unroll
            for (int mi = 0; mi < 4; mi++) mma_mi(cur, mi);
        }
    }

    // ---- chunk 1: ksteps 0-2 normal, kstep 3 fused with epilogue ----
    CP_WAIT(0);
    __syncthreads();
    {
        uint32_t st = sbase + STAGE_BYTES;
#pragma unroll
        for (int mi = 0; mi < 4; mi++) ldsm_x4(af[0][mi], st + aOff[mi]);
#pragma unroll
        for (int p = 0; p < 2; p++) ldsm_x4(bf[0][p], st + bOff[p]);
#pragma unroll
        for (int s = 0; s < 3; s++) {
            int cur = s & 1, nxt = cur ^ 1;
            uint32_t kb32 = (uint32_t)((s + 1) * 32);
#pragma unroll
            for (int mi = 0; mi < 4; mi++) ldsm_x4(af[nxt][mi], st + aOff[mi] + kb32);
#pragma unroll
            for (int p = 0; p < 2; p++) ldsm_x4(bf[nxt][p], st + bOff[p] + kb32);
#pragma unroll
            for (int mi = 0; mi < 4; mi++) mma_mi(cur, mi);
        }
        // kstep 3 (buffer 1): interleave epilogue one mi behind the MMAs
        mma_mi(1, 0);
        mma_mi(1, 1);
        epi_mi(0);
        mma_mi(1, 2);
        epi_mi(1);
        mma_mi(1, 3);
        epi_mi(2);
        epi_mi(3);
    }
}

// ---------------------------------------------------------------------------
// Launcher. Fork-join stream pipeline inside graph capture:
//   stream0 (capture stream): norm chunk c  -> event ev[c]
//   s1: waits ev[c], runs gemm chunk c (4 heads)
//   join: event on s1 after last gemm, stream0 waits.
// Norm chunk c+1 overlaps gemm chunk c; the ~21us norm pass hides behind
// the GEMM except for the first ~2.6us chunk.
// Persistent stream/events (resource init only; identical captured work
// every call).
// ---------------------------------------------------------------------------
extern "C" void kernel_launch(void* const* d_in, const int* in_sizes, int n_in,
                              void* d_out, int out_size) {
    const float* q  = (const float*)d_in[0];
    const float* k  = (const float*)d_in[1];
    const float* lt = (const float*)d_in[2];
    float* out = (float*)d_out;

    static cudaStream_t s1 = nullptr;
    static cudaEvent_t ev[NCHUNK], evj;
    if (s1 == nullptr) {
        cudaStreamCreateWithFlags(&s1, cudaStreamNonBlocking);
        for (int i = 0; i < NCHUNK; i++)
            cudaEventCreateWithFlags(&ev[i], cudaEventDisableTiming);
        cudaEventCreateWithFlags(&evj, cudaEventDisableTiming);
        cudaFuncSetAttribute(hgemm_exp_kernel,
                             cudaFuncAttributeMaxDynamicSharedMemorySize, SMEM_TOTAL);
    }

    // 2 * ROWS_PER_CHUNK rows per chunk, 1 warp/row, 8 warps/block
    int nblk = (2 * ROWS_PER_CHUNK) / 8;
    dim3 ggrid(16, 16, BH_CHUNK);

    for (int c = 0; c < NCHUNK; c++) {
        norm_cvt_kernel<<<nblk, 256>>>(q, k, lt, c * ROWS_PER_CHUNK);
        cudaEventRecord(ev[c], 0);
        cudaStreamWaitEvent(s1, ev[c], 0);
        hgemm_exp_kernel<<<ggrid, 256, SMEM_TOTAL, s1>>>(out, c * BH_CHUNK);
    }
    cudaEventRecord(evj, s1);
    cudaStreamWaitEvent(0, evj, 0);
}

// round 17
// speedup vs baseline: 1.0697x; 1.0697x over previous
#include <cuda_runtime.h>
#include <cuda_fp16.h>
#include <cstdint>

#define SEQ 2048
#define DIM 128
#define BHN 32
#define NROWS (BHN * SEQ)   // 65536 rows each for q and k

// Normalized + sqrt(scale)-folded fp16 copies (16 MB each, device globals)
__device__ __half g_qh[(size_t)NROWS * DIM];
__device__ __half g_kh[(size_t)NROWS * DIM];

// ---------------------------------------------------------------------------
// Kernel 1: per-row normalize, fold sqrt(log2e/temp), convert to fp16.
// One warp per row. Processes rows [row_base, row_base + nrows) of BOTH
// q and k. Streaming loads (fp32 inputs read exactly once).
// ---------------------------------------------------------------------------
__global__ void norm_cvt_kernel(const float* __restrict__ q,
                                const float* __restrict__ k,
                                const float* __restrict__ logt,
                                int row_base, int nrows) {
    int gwarp = (blockIdx.x * blockDim.x + threadIdx.x) >> 5;
    int lane = threadIdx.x & 31;
    bool is_q = gwarp < nrows;
    int row = row_base + (is_q ? gwarp : gwarp - nrows);
    const float* src = is_q ? q : k;
    float4 v = __ldcs(reinterpret_cast<const float4*>(src + (size_t)row * DIM) + lane);
    float ss = v.x * v.x + v.y * v.y + v.z * v.z + v.w * v.w;
#pragma unroll
    for (int o = 16; o > 0; o >>= 1) ss += __shfl_xor_sync(0xffffffffu, ss, o);

    const float LOG2E = 1.442695040888963f;
    float temp = fminf(fmaxf(__expf(*logt), 0.05f), 100.0f);
    float rsc = sqrtf(LOG2E / temp);
    float f = rsc / fmaxf(sqrtf(ss), 1e-12f);

    __half2 h0 = __floats2half2_rn(v.x * f, v.y * f);
    __half2 h1 = __floats2half2_rn(v.z * f, v.w * f);
    __half* dst = (is_q ? g_qh : g_kh) + (size_t)row * DIM + lane * 4;
    uint2 u;
    u.x = *reinterpret_cast<uint32_t*>(&h0);
    u.y = *reinterpret_cast<uint32_t*>(&h1);
    *reinterpret_cast<uint2*>(dst) = u;
}

// ---------------------------------------------------------------------------
// Helpers
// ---------------------------------------------------------------------------
__device__ __forceinline__ uint32_t smem_to_u32(const void* p) {
    uint32_t a;
    asm("{ .reg .u64 t; cvta.to.shared.u64 t, %1; cvt.u32.u64 %0, t; }" : "=r"(a) : "l"(p));
    return a;
}

// .ca: keep fills in L1 — A/B (round 15) proved cross-CTA tile reuse wins
#define CP_ASYNC16(dst, src) \
    asm volatile("cp.async.ca.shared.global [%0], [%1], 16;" :: "r"(dst), "l"(src))
#define CP_COMMIT() asm volatile("cp.async.commit_group;" ::: "memory")
#define CP_WAIT(n)  asm volatile("cp.async.wait_group %0;" :: "n"(n) : "memory")

__device__ __forceinline__ void ldsm_x4(unsigned r[4], uint32_t addr) {
    asm volatile("ldmatrix.sync.aligned.m8n8.x4.shared.b16 {%0,%1,%2,%3}, [%4];"
                 : "=r"(r[0]), "=r"(r[1]), "=r"(r[2]), "=r"(r[3]) : "r"(addr));
}

__device__ __forceinline__ void mma_f16(float c[4], const unsigned a[4],
                                        unsigned b0, unsigned b1) {
    asm volatile(
        "mma.sync.aligned.m16n8k16.row.col.f32.f16.f16.f32 "
        "{%0,%1,%2,%3}, {%4,%5,%6,%7}, {%8,%9}, {%0,%1,%2,%3};\n"
        : "+f"(c[0]), "+f"(c[1]), "+f"(c[2]), "+f"(c[3])
        : "r"(a[0]), "r"(a[1]), "r"(a[2]), "r"(a[3]), "r"(b0), "r"(b1));
}

__device__ __forceinline__ float ex2f(float x) {
    float y;
    asm("ex2.approx.f32 %0, %1;" : "=f"(y) : "f"(x));
    return y;
}

// streaming store: output is written once, never re-read -> evict-first in L2
__device__ __forceinline__ void stg_cs_v2(float* p, float x, float y) {
    asm volatile("st.global.cs.v2.f32 [%0], {%1, %2};" :: "l"(p), "f"(x), "f"(y) : "memory");
}

// ---------------------------------------------------------------------------
// Kernel 2: fp16 GEMM + exp epilogue (round-13 configuration, bh-offset).
// 2 CTAs/SM, 256 threads. CTA tile M=128 x N=128, K=128 in two chunks of
// 64, 2 smem stages. Warp grid 2x4, warp tile 64x32. In-warp fragment
// software pipeline; fused-tail epilogue under the last k-step's MMAs.
// smem stage = 36864 B, total 73728 B -> 2 CTAs/SM.
// acc is in log2 domain: epilogue = ex2(acc) + 1e-6.
// ---------------------------------------------------------------------------
#define LDH 72
#define CH_BYTES (128 * LDH * 2)          // 18432
#define STAGE_BYTES (2 * CH_BYTES)        // 36864
#define SMEM_TOTAL (2 * STAGE_BYTES)      // 73728

__global__ __launch_bounds__(256, 2) void hgemm_exp_kernel(float* __restrict__ out,
                                                           int bh_base) {
    extern __shared__ char smem[];
    uint32_t sbase = smem_to_u32(smem);

    int bh = bh_base + blockIdx.z;
    int bm = blockIdx.y;
    int bn = blockIdx.x;
    int tid = threadIdx.x;
    int warp = tid >> 5, lane = tid & 31;
    int wm = warp >> 2, wn = warp & 3;   // 2 x 4 warp grid
    int wmo = wm * 64, wno = wn * 32;    // warp tile 64 x 32

    const __half* qb = g_qh + ((size_t)bh * SEQ + (size_t)bm * 128) * DIM;
    const __half* kb = g_kh + ((size_t)bh * SEQ + (size_t)bn * 128) * DIM;

    // cp.async: chunk matrix = 128 rows x 64 halves = 1024 16B-chunks -> 4/thr
    int ldr = tid >> 3;          // base row 0..31
    int ldc8 = tid & 7;          // 8-half column group

    auto issue_chunk = [&](int c, int s) {
        uint32_t stA = sbase + (uint32_t)(s * STAGE_BYTES);
        uint32_t stB = stA + CH_BYTES;
        const __half* qsrc = qb + c * 64 + ldc8 * 8;
        const __half* ksrc = kb + c * 64 + ldc8 * 8;
#pragma unroll
        for (int i = 0; i < 4; i++) {
            int r = ldr + i * 32;
            uint32_t o = (uint32_t)((r * LDH + ldc8 * 8) * 2);
            CP_ASYNC16(stA + o, qsrc + (size_t)r * DIM);
            CP_ASYNC16(stB + o, ksrc + (size_t)r * DIM);
        }
        CP_COMMIT();
    };

    issue_chunk(0, 0);
    issue_chunk(1, 1);

    // fragment offsets within a stage (halves*2 = bytes)
    int l15 = lane & 15, lk = (lane >> 4) * 8;
    uint32_t aOff[4], bOff[2];
#pragma unroll
    for (int mi = 0; mi < 4; mi++)
        aOff[mi] = (uint32_t)(((wmo + mi * 16 + l15) * LDH + lk) * 2);
#pragma unroll
    for (int p = 0; p < 2; p++)
        bOff[p] = (uint32_t)(((wno + p * 16 + l15) * LDH + lk) * 2) + CH_BYTES;

    float acc[4][4][4];
#pragma unroll
    for (int mi = 0; mi < 4; mi++)
#pragma unroll
        for (int ni = 0; ni < 4; ni++)
#pragma unroll
            for (int r = 0; r < 4; r++) acc[mi][ni][r] = 0.0f;

    unsigned af[2][4][4], bf[2][2][4];

    // per-mi MMA group for k-step buffer `cur`
    auto mma_mi = [&](int cur, int mi) {
#pragma unroll
        for (int p = 0; p < 2; p++) {
            mma_f16(acc[mi][2 * p],     af[cur][mi], bf[cur][p][0], bf[cur][p][2]);
            mma_f16(acc[mi][2 * p + 1], af[cur][mi], bf[cur][p][1], bf[cur][p][3]);
        }
    };

    // epilogue store base: row (bm*128 + wmo + gid), col (bn*128 + wno + tig*2)
    int gid = lane >> 2, tig = lane & 3;
    float* bp = out + ((size_t)bh * SEQ + (size_t)(bm * 128 + wmo + gid)) * SEQ
                    + bn * 128 + wno + tig * 2;

    // per-mi epilogue: 16 ex2 + 8 stg.cs.v2
    auto epi_mi = [&](int mi) {
        float* o0p = bp + (size_t)(mi * 16) * SEQ;
        float* o1p = o0p + (size_t)8 * SEQ;
#pragma unroll
        for (int ni = 0; ni < 4; ni++) {
            stg_cs_v2(o0p, ex2f(acc[mi][ni][0]) + 1e-6f,
                           ex2f(acc[mi][ni][1]) + 1e-6f);
            stg_cs_v2(o1p, ex2f(acc[mi][ni][2]) + 1e-6f,
                           ex2f(acc[mi][ni][3]) + 1e-6f);
            o0p += 8; o1p += 8;
        }
    };

    // ---- chunk 0: 4 ksteps, fragments pipelined one step ahead ----
    CP_WAIT(1);
    __syncthreads();
    {
        uint32_t st = sbase;
#pragma unroll
        for (int mi = 0; mi < 4; mi++) ldsm_x4(af[0][mi], st + aOff[mi]);
#pragma unroll
        for (int p = 0; p < 2; p++) ldsm_x4(bf[0][p], st + bOff[p]);
#pragma unroll
        for (int s = 0; s < 4; s++) {
            int cur = s & 1, nxt = cur ^ 1;
            if (s < 3) {
                uint32_t kb32 = (uint32_t)((s + 1) * 32);
#pragma unroll
                for (int mi = 0; mi < 4; mi++) ldsm_x4(af[nxt][mi], st + aOff[mi] + kb32);
#pragma unroll
                for (int p = 0; p < 2; p++) ldsm_x4(bf[nxt][p], st + bOff[p] + kb32);
            }
#pragma unroll
            for (int mi = 0; mi < 4; mi++) mma_mi(cur, mi);
        }
    }

    // ---- chunk 1: ksteps 0-2 normal, kstep 3 fused with epilogue ----
    CP_WAIT(0);
    __syncthreads();
    {
        uint32_t st = sbase + STAGE_BYTES;
#pragma unroll
        for (int mi = 0; mi < 4; mi++) ldsm_x4(af[0][mi], st + aOff[mi]);
#pragma unroll
        for (int p = 0; p < 2; p++) ldsm_x4(bf[0][p], st + bOff[p]);
#pragma unroll
        for (int s = 0; s < 3; s++) {
            int cur = s & 1, nxt = cur ^ 1;
            uint32_t kb32 = (uint32_t)((s + 1) * 32);
#pragma unroll
            for (int mi = 0; mi < 4; mi++) ldsm_x4(af[nxt][mi], st + aOff[mi] + kb32);
#pragma unroll
            for (int p = 0; p < 2; p++) ldsm_x4(bf[nxt][p], st + bOff[p] + kb32);
#pragma unroll
            for (int mi = 0; mi < 4; mi++) mma_mi(cur, mi);
        }
        // kstep 3 (buffer 1): interleave epilogue one mi behind the MMAs
        mma_mi(1, 0);
        mma_mi(1, 1);
        epi_mi(0);
        mma_mi(1, 2);
        epi_mi(1);
        mma_mi(1, 3);
        epi_mi(2);
        epi_mi(3);
    }
}

// ---------------------------------------------------------------------------
// Launcher. Asymmetric fork-join pipeline inside graph capture:
// head chunks [4, 12, 16]. Chunk 0 is tiny (gets the GEMM started ~2.7us
// in); later chunks' norms hide under the previous gemm chunk, and their
// grids (3072/4096 CTAs) are deep enough that wave-tail waste is small.
//   stream0: norm chunk c -> ev[c];  s1: wait ev[c], gemm chunk c; join.
// ---------------------------------------------------------------------------
extern "C" void kernel_launch(void* const* d_in, const int* in_sizes, int n_in,
                              void* d_out, int out_size) {
    const float* q  = (const float*)d_in[0];
    const float* k  = (const float*)d_in[1];
    const float* lt = (const float*)d_in[2];
    float* out = (float*)d_out;

    static cudaStream_t s1 = nullptr;
    static cudaEvent_t ev[3], evj;
    if (s1 == nullptr) {
        cudaStreamCreateWithFlags(&s1, cudaStreamNonBlocking);
        for (int i = 0; i < 3; i++)
            cudaEventCreateWithFlags(&ev[i], cudaEventDisableTiming);
        cudaEventCreateWithFlags(&evj, cudaEventDisableTiming);
        cudaFuncSetAttribute(hgemm_exp_kernel,
                             cudaFuncAttributeMaxDynamicSharedMemorySize, SMEM_TOTAL);
    }

    const int hbase[3] = {0, 4, 16};
    const int hcnt[3]  = {4, 12, 16};

    for (int c = 0; c < 3; c++) {
        int rows = hcnt[c] * SEQ;
        // one warp/row over q and k rows of this chunk; 8 warps/block
        norm_cvt_kernel<<<(2 * rows) / 8, 256>>>(q, k, lt, hbase[c] * SEQ, rows);
        cudaEventRecord(ev[c], 0);
        cudaStreamWaitEvent(s1, ev[c], 0);
        dim3 ggrid(16, 16, hcnt[c]);
        hgemm_exp_kernel<<<ggrid, 256, SMEM_TOTAL, s1>>>(out, hbase[c]);
    }
    cudaEventRecord(evj, s1);
    cudaStreamWaitEvent(0, evj, 0);
}